// round 2
// baseline (speedup 1.0000x reference)
#include <cuda_runtime.h>
#include <math.h>

#define NB 16
#define H 512
#define W 512
#define RPB 32              // rows per block
#define ITERS 8             // RPB / 4 row-groups
#define MUF 5.0f
#define KKINV (1.0f/961.0f)

// per-block partials: {wbce_num, weit_sum, inter, union}
__device__ float g_part[256 * 4];

// ================= fused kernel =================
// grid = 16 batches * 16 row-segments = 256 blocks, 512 threads
// threads: 4 groups of 128; group g handles row r0 + it*4 + g
// each thread owns 4 consecutive columns (float4 everywhere)
__global__ __launch_bounds__(512) void fused_kernel(const float* __restrict__ pred,
                                                    const float* __restrict__ mask) {
    __shared__ float sP[4][544];    // [pad16 | 512 prefix | pad16(P[511])]
    __shared__ float wsum[4][4];    // per-group warp-scan totals
    __shared__ float red[16][4];    // per-warp reduction buffer

    const int t    = threadIdx.x;
    const int g    = t >> 7;        // row-group 0..3
    const int tg   = t & 127;       // thread within group
    const int wg   = (t >> 5) & 3;  // warp within group
    const int lane = t & 31;
    const int c0   = tg * 4;

    const int b  = blockIdx.x >> 4;
    const int r0 = (blockIdx.x & 15) * RPB;

    const float* mb = mask + (size_t)b * H * W;
    const float* pb = pred + (size_t)(b * 2 + 1) * H * W;   // channel 1 logits

    // zero the left pad once (protected by first in-loop barrier)
    if (tg < 4) *(float4*)&sP[g][tg * 4] = make_float4(0.f, 0.f, 0.f, 0.f);

    // ---- init vertical sliding window sum for row rr = r0 + g ----
    int rr = r0 + g;
    float4 vs = make_float4(0.f, 0.f, 0.f, 0.f);
    {
        int lo = rr - 15; if (lo < 0) lo = 0;
        int hi = rr + 15; if (hi > H - 1) hi = H - 1;
        for (int j = lo; j <= hi; ++j) {
            float4 mm = *(const float4*)(mb + (size_t)j * W + c0);
            vs.x += mm.x; vs.y += mm.y; vs.z += mm.z; vs.w += mm.w;
        }
    }

    float a0 = 0.f, a1 = 0.f, a2 = 0.f, a3 = 0.f;

    #pragma unroll
    for (int it = 0; it < ITERS; ++it) {
        // ---- horizontal prefix of vertical sums (per group) ----
        float l0 = vs.x;
        float l1 = l0 + vs.y;
        float l2 = l1 + vs.z;
        float l3 = l2 + vs.w;
        float tot = l3;

        float x = tot;
        #pragma unroll
        for (int d = 1; d < 32; d <<= 1) {
            float n = __shfl_up_sync(0xffffffffu, x, d);
            if (lane >= d) x += n;
        }
        if (lane == 31) wsum[g][wg] = x;
        __syncthreads();

        float woff = x - tot;                  // exclusive within warp
        #pragma unroll
        for (int w = 0; w < 4; ++w) if (w < wg) woff += wsum[g][w];

        float4 P4 = make_float4(woff + l0, woff + l1, woff + l2, woff + l3);
        *(float4*)&sP[g][16 + c0] = P4;
        if (tg == 127) {                       // replicate P[511] into right pad
            float4 rep = make_float4(P4.w, P4.w, P4.w, P4.w);
            *(float4*)&sP[g][528] = rep;
            *(float4*)&sP[g][532] = rep;
            *(float4*)&sP[g][536] = rep;
            *(float4*)&sP[g][540] = rep;
        }
        __syncthreads();

        // ---- 31-wide window via prefix differences (aligned LDS.128) ----
        float4 Pa = *(const float4*)&sP[g][16 + c0 + 12];  // P[c0+12..15]
        float4 Pb = *(const float4*)&sP[g][16 + c0 + 16];  // P[c0+16..19]
        float4 Pl = *(const float4*)&sP[g][c0];            // P[c0-16..-13] (0 in pad)

        float win[4];
        win[0] = Pa.w - Pl.x;
        win[1] = Pb.x - Pl.y;
        win[2] = Pb.y - Pl.z;
        win[3] = Pb.z - Pl.w;

        // ---- fused elementwise + accumulate ----
        float4 m4 = *(const float4*)(mb + (size_t)rr * W + c0);
        float4 p4 = *(const float4*)(pb + (size_t)rr * W + c0);
        float mv[4] = {m4.x, m4.y, m4.z, m4.w};
        float pv[4] = {p4.x, p4.y, p4.z, p4.w};

        #pragma unroll
        for (int i = 0; i < 4; ++i) {
            float box  = win[i] * KKINV;
            float m    = mv[i];
            float p    = pv[i];
            float weit = 1.0f + MUF * fabsf(box - m);

            float bce = fmaxf(p, 0.0f) - p * m + log1pf(__expf(-fabsf(p)));
            float ps  = 1.0f / (1.0f + __expf(-p));

            a0 += weit * bce;
            a1 += weit;
            a2 += ps * m * weit;
            a3 += (ps + m) * weit;
        }

        // ---- slide vertical window by 4 rows ----
        if (it < ITERS - 1) {
            #pragma unroll
            for (int k = 1; k <= 4; ++k) {
                int ar = rr + 15 + k;           // rows rr+16 .. rr+19
                if (ar < H) {
                    float4 mm = *(const float4*)(mb + (size_t)ar * W + c0);
                    vs.x += mm.x; vs.y += mm.y; vs.z += mm.z; vs.w += mm.w;
                }
                int sr = rr - 15 + (k - 1);     // rows rr-15 .. rr-12
                if (sr >= 0) {
                    float4 mm = *(const float4*)(mb + (size_t)sr * W + c0);
                    vs.x -= mm.x; vs.y -= mm.y; vs.z -= mm.z; vs.w -= mm.w;
                }
            }
            rr += 4;
        }
    }

    // ---- deterministic block reduction ----
    #pragma unroll
    for (int d = 16; d > 0; d >>= 1) {
        a0 += __shfl_down_sync(0xffffffffu, a0, d);
        a1 += __shfl_down_sync(0xffffffffu, a1, d);
        a2 += __shfl_down_sync(0xffffffffu, a2, d);
        a3 += __shfl_down_sync(0xffffffffu, a3, d);
    }
    int wid = t >> 5;
    if (lane == 0) {
        red[wid][0] = a0; red[wid][1] = a1; red[wid][2] = a2; red[wid][3] = a3;
    }
    __syncthreads();
    if (t == 0) {
        float s0 = 0.f, s1 = 0.f, s2 = 0.f, s3 = 0.f;
        #pragma unroll
        for (int w = 0; w < 16; ++w) {
            s0 += red[w][0]; s1 += red[w][1]; s2 += red[w][2]; s3 += red[w][3];
        }
        ((float4*)g_part)[blockIdx.x] = make_float4(s0, s1, s2, s3);
    }
}

// ================= finalize: per-batch loss + mean =================
__global__ void finalize_kernel(float* __restrict__ out) {
    __shared__ float sl[NB];
    int t = threadIdx.x;        // 32 threads
    if (t < NB) {
        float s0 = 0.f, s1 = 0.f, s2 = 0.f, s3 = 0.f;
        const float4* gp = (const float4*)g_part;
        #pragma unroll
        for (int k = 0; k < 16; ++k) {
            float4 v = gp[t * 16 + k];
            s0 += v.x; s1 += v.y; s2 += v.z; s3 += v.w;
        }
        float wbce = s0 / s1;
        float wiou = 1.0f - (s2 + 1.0f) / (s3 - s2 + 1.0f);
        sl[t] = wbce + wiou;
    }
    __syncthreads();
    if (t == 0) {
        float s = 0.f;
        #pragma unroll
        for (int k = 0; k < NB; ++k) s += sl[k];
        out[0] = s * (1.0f / NB);
    }
}

extern "C" void kernel_launch(void* const* d_in, const int* in_sizes, int n_in,
                              void* d_out, int out_size) {
    const float* pred = (const float*)d_in[0];
    const float* mask = (const float*)d_in[1];
    if (n_in >= 2 && in_sizes[0] == NB * H * W && in_sizes[1] == NB * 2 * H * W) {
        mask = (const float*)d_in[0];
        pred = (const float*)d_in[1];
    }
    float* out = (float*)d_out;

    fused_kernel<<<NB * (H / RPB), 512>>>(pred, mask);
    finalize_kernel<<<1, 32>>>(out);
}